// round 12
// baseline (speedup 1.0000x reference)
#include <cuda_runtime.h>
#include <cuda.h>
#include <cstdint>
#include <math.h>

#define BB   128
#define TIN  256
#define DIN  64
#define HH   1024
#define G4   4096
#define TOUT 128
#define DOUT 128

#define K1   (HH + DIN)   // 1088
#define NKC1 (K1 / 8)     // 136
#define NKC2 (HH / 8)     // 128
#define NCTA 128
#define CLS  4            // cluster size
#define MCAST_MASK 0xFu

// -------------------- device scratch --------------------
__device__ float g_W1p [512 * NKC1 * 64];   // [Wh1;Wi1] permuted to B-frag order
__device__ float g_W2p [512 * NKC2 * 64];   // Wh2 permuted
__device__ float g_Wi2p[512 * NKC2 * 64];   // Wi2 permuted
__device__ float g_Wlp [ 16 * NKC2 * 64];   // Wlin permuted
__device__ __align__(256) float g_xr  [BB * TIN * DIN];
__device__ __align__(256) float g_Hbuf[2 * BB * HH];    // ping-pong hidden state
__device__ float g_C   [BB * HH];
__device__ float g_XG2 [BB * G4];
__device__ float g_HS2 [TOUT * BB * HH];
__device__ unsigned int g_bar;              // CG-style phase barrier counter

// -------------------- helpers --------------------
__device__ __forceinline__ float tf32r(float x) {
    uint32_t u;
    asm("cvt.rna.tf32.f32 %0, %1;" : "=r"(u) : "f"(x));
    return __uint_as_float(u);
}
__device__ __forceinline__ float sigf(float x) { return 1.0f / (1.0f + expf(-x)); }

__device__ __forceinline__ void mma8(float c[4], const uint32_t a[4], uint32_t b0, uint32_t b1) {
    asm volatile(
        "mma.sync.aligned.m16n8k8.row.col.f32.tf32.tf32.f32 "
        "{%0,%1,%2,%3}, {%4,%5,%6,%7}, {%8,%9}, {%0,%1,%2,%3};"
        : "+f"(c[0]), "+f"(c[1]), "+f"(c[2]), "+f"(c[3])
        : "r"(a[0]), "r"(a[1]), "r"(a[2]), "r"(a[3]), "r"(b0), "r"(b1));
}

__device__ __forceinline__ uint32_t s2u(const void* p) {
    uint32_t a;
    asm("{ .reg .u64 t; cvta.to.shared.u64 t, %1; cvt.u32.u64 %0, t; }" : "=r"(a) : "l"(p));
    return a;
}
__device__ __forceinline__ uint32_t ctarank() {
    uint32_t r;
    asm("mov.u32 %0, %%cluster_ctarank;" : "=r"(r));
    return r;
}
__device__ __forceinline__ void mbar_init(uint32_t a, int cnt) {
    asm volatile("mbarrier.init.shared.b64 [%0], %1;" :: "r"(a), "r"(cnt) : "memory");
}
__device__ __forceinline__ void mbar_arrive_cluster(uint32_t local_addr, uint32_t rank) {
    asm volatile(
        "{\n\t.reg .b32 ra;\n\t"
        "mapa.shared::cluster.u32 ra, %0, %1;\n\t"
        "mbarrier.arrive.shared::cluster.b64 _, [ra];\n\t}"
        :: "r"(local_addr), "r"(rank) : "memory");
}
__device__ __forceinline__ void mbar_expect(uint32_t a, uint32_t bytes) {
    asm volatile("mbarrier.arrive.expect_tx.shared.b64 _, [%0], %1;" :: "r"(a), "r"(bytes) : "memory");
}
__device__ __forceinline__ void mbar_wait(uint32_t a, int ph) {
    asm volatile(
        "{\n\t.reg .pred P;\n"
        "W%=:\n\t"
        "mbarrier.try_wait.parity.acquire.cta.shared::cta.b64 P, [%0], %1, 0x989680;\n\t"
        "@P bra D%=;\n\t"
        "bra W%=;\n"
        "D%=:\n\t}"
        :: "r"(a), "r"(ph) : "memory");
}
// Multicast 3D TMA load: this CTA's slice delivered to all cluster CTAs.
__device__ __forceinline__ void tma3d_mc(uint32_t dst, const CUtensorMap* m,
                                         int x, int y, int z, uint32_t bar, uint16_t mask) {
    asm volatile(
        "cp.async.bulk.tensor.3d.shared::cluster.global.tile.mbarrier::complete_tx::bytes.multicast::cluster "
        "[%0], [%1, {%2,%3,%4}], [%5], %6;"
        :: "r"(dst), "l"(m), "r"(x), "r"(y), "r"(z), "r"(bar), "h"(mask) : "memory");
}
__device__ __forceinline__ void fence_async() {
    asm volatile("fence.proxy.async;" ::: "memory");
}
__device__ __forceinline__ void cluster_sync() {
    asm volatile("barrier.cluster.arrive.aligned;" ::: "memory");
    asm volatile("barrier.cluster.wait.aligned;" ::: "memory");
}

// Cooperative-groups-style grid barrier (proven correct in R9-R11).
__device__ __forceinline__ void grid_barrier() {
    __syncthreads();
    if (threadIdx.x == 0) {
        __threadfence();
        unsigned int nb = (blockIdx.x == 0) ? (0x80000000u - (NCTA - 1u)) : 1u;
        unsigned int old = atomicAdd(&g_bar, nb);
        volatile unsigned int* vb = &g_bar;
        while ((((old ^ *vb) & 0x80000000u) == 0u)) { }
        __threadfence();
    }
    __syncthreads();
}

// -------------------- prep kernels --------------------
__global__ void permW_kernel(const float* __restrict__ Wh, const float* __restrict__ Wx,
                             int which, int nkc, int ldsrc, int total) {
    int i = blockIdx.x * blockDim.x + threadIdx.x;
    if (i >= total) return;
    float* dst = (which == 0) ? g_W1p : (which == 1) ? g_W2p : (which == 2) ? g_Wi2p : g_Wlp;
    int reg  = i & 1;
    int lane = (i >> 1) & 31;
    int kc   = (i >> 6) % nkc;
    int nt   = i / (nkc * 64);
    int k = kc * 8 + reg * 4 + (lane & 3);
    int n = nt * 8 + (lane >> 2);
    float v = (k < HH) ? Wh[k * ldsrc + n] : Wx[(k - HH) * ldsrc + n];
    dst[i] = tf32r(v);
}

__global__ void roundx_kernel(const float* __restrict__ x, int total) {
    int i = blockIdx.x * blockDim.x + threadIdx.x;
    if (i < total) g_xr[i] = tf32r(x[i]);
}

__global__ void zero_kernel() {
    int i = blockIdx.x * blockDim.x + threadIdx.x;
    if (i < BB * HH) { g_Hbuf[i] = 0.0f; g_Hbuf[BB * HH + i] = 0.0f; g_C[i] = 0.0f; }
    if (i == 0) g_bar = 0u;
}

// -------------------- persistent LSTM layer kernel --------------------
// 128 CTAs (32 clusters of 4) x 256 thr, one CTA per SM (single wave).
// CTA owns 8 hidden columns. B weights SMEM-resident. A (h, + x_t for L1)
// streamed per step via TMA SW128 MULTICAST: each cluster CTA loads a
// distinct 32-row slice of each 128-row chunk and multicasts it to all 4
// CTAs (L2 A-traffic / 4). Empty-stage signaling is cluster-wide: every
// consumer warp arrives on all 4 CTAs' empty barriers (count 32). Full
// barrier: local expect_tx(32KB), 4x8KB multicast complete_tx. Cell state
// in registers; CG grid barrier between steps; proxy fences order generic
// h-stores before async-proxy TMA reads.
template<int LAYER>
__global__ void __launch_bounds__(256) __cluster_dims__(CLS, 1, 1)
lstm_persist(const __grid_constant__ CUtensorMap tmH,
             const __grid_constant__ CUtensorMap tmX,
             const float* __restrict__ bias, int nsteps)
{
    constexpr int NKC = (LAYER == 1) ? NKC1 : NKC2;
    constexpr int NCH = (LAYER == 1) ? 17 : 16;     // 64-k chunks per step

    extern __shared__ float smraw[];
    const uint32_t rawB = s2u(smraw);
    const uint32_t aB   = (rawB + 1023u) & ~1023u;  // 1024B-aligned TMA region
    float* sA = smraw + ((aB - rawB) >> 2);          // 2 stages x 8192 floats
    float* sB = sA + 16384;                          // B slab, fragment order
    const uint32_t barB = s2u(sB + 4 * NKC * 64);    // full0@0 empty0@8 full1@16 empty1@24

    const int tid = threadIdx.x, w = tid >> 5, lane = tid & 31, cta = blockIdx.x;
    const uint32_t rank = ctarank();
    const int ybase = (int)rank * 32;                // this CTA's slice rows

    // ---- load B slabs into SMEM (once per layer) ----
    {
        const float* Wp = (LAYER == 1) ? g_W1p : g_W2p;
        #pragma unroll
        for (int q = 0; q < 4; ++q) {
            const float4* src = (const float4*)(Wp + (size_t)(cta + q * 128) * (NKC * 64));
            float4* dst = (float4*)(sB + q * NKC * 64);
            for (int i = tid; i < NKC * 16; i += 256) dst[i] = src[i];
        }
    }
    if (tid == 0) {
        mbar_init(barB + 0, 1);   mbar_init(barB + 8, 32);
        mbar_init(barB + 16, 1);  mbar_init(barB + 24, 32);
        asm volatile("fence.proxy.async.shared::cta;" ::: "memory");
    }
    __syncthreads();
    cluster_sync();   // peers' mbarriers must be live before any multicast TMA

    // ---- per-thread constants ----
    const int j0 = cta * 8 + (lane & 3) * 2;
    int mrow[4];
    #pragma unroll
    for (int cr = 0; cr < 4; ++cr) mrow[cr] = w * 16 + (lane >> 2) + ((cr >> 1) << 3);

    float bI[2], bF[2], bG[2], bO[2];
    float xg[4][4];
    float creg[4] = {0.f, 0.f, 0.f, 0.f};
    if (LAYER == 1) {
        #pragma unroll
        for (int u = 0; u < 2; ++u) {
            bI[u] = bias[j0 + u];          bF[u] = bias[HH + j0 + u];
            bG[u] = bias[2 * HH + j0 + u]; bO[u] = bias[3 * HH + j0 + u];
        }
    } else {
        #pragma unroll
        for (int cr = 0; cr < 4; ++cr) {
            int m = mrow[cr], j = j0 + (cr & 1);
            xg[cr][0] = __ldcg(&g_XG2[m * G4 + j]);
            xg[cr][1] = __ldcg(&g_XG2[m * G4 + HH + j]);
            xg[cr][2] = __ldcg(&g_XG2[m * G4 + 2 * HH + j]);
            xg[cr][3] = __ldcg(&g_XG2[m * G4 + 3 * HH + j]);
            creg[cr]  = __ldcg(&g_C[m * HH + j]);
        }
    }
    __syncthreads();

    int ps = 0, pp = 1, cs = 0, cp = 0;   // producer / consumer stage+phase
    int rd = 0;

    for (int t = 0; t < nsteps; ++t) {
        float acc[4][4];
        #pragma unroll
        for (int q = 0; q < 4; ++q) {
            #pragma unroll
            for (int r = 0; r < 4; ++r) acc[q][r] = 0.f;
        }

        // prologue: issue chunk 0 slices (always from h)
        if (tid == 0) {
            fence_async();   // order prior generic h-stores before async-proxy reads
            mbar_wait(barB + 8 + ps * 16, pp);
            mbar_expect(barB + ps * 16, 32768);
            uint32_t d = aB + ps * 32768 + rank * 4096;
            tma3d_mc(d,         &tmH, 0,  ybase, rd, barB + ps * 16, MCAST_MASK);
            tma3d_mc(d + 16384, &tmH, 32, ybase, rd, barB + ps * 16, MCAST_MASK);
            ps ^= 1; if (ps == 0) pp ^= 1;
        }

        for (int c = 0; c < NCH; ++c) {
            if (tid == 0 && c + 1 < NCH) {
                int cn = c + 1;
                mbar_wait(barB + 8 + ps * 16, pp);
                mbar_expect(barB + ps * 16, 32768);
                uint32_t d = aB + ps * 32768 + rank * 4096;
                if (LAYER == 1 && cn == 16) {
                    tma3d_mc(d,         &tmX, 0,  t, ybase, barB + ps * 16, MCAST_MASK);
                    tma3d_mc(d + 16384, &tmX, 32, t, ybase, barB + ps * 16, MCAST_MASK);
                } else {
                    tma3d_mc(d,         &tmH, cn * 64,      ybase, rd, barB + ps * 16, MCAST_MASK);
                    tma3d_mc(d + 16384, &tmH, cn * 64 + 32, ybase, rd, barB + ps * 16, MCAST_MASK);
                }
                ps ^= 1; if (ps == 0) pp ^= 1;
            }

            mbar_wait(barB + cs * 16, cp);
            const float* ab = sA + cs * 8192;

            #pragma unroll
            for (int kk = 0; kk < 8; ++kk) {
                int kc = c * 8 + kk;
                const float* hb = ab + (kk >> 2) * 4096;
                uint32_t a[4];
                #pragma unroll
                for (int r = 0; r < 4; ++r) {
                    int m    = w * 16 + (lane >> 2) + (r & 1) * 8;
                    int colw = (kk & 3) * 8 + (lane & 3) + ((r >> 1) << 2);
                    a[r] = __float_as_uint(hb[m * 32 + (colw ^ ((m & 7) << 2))]);
                }
                #pragma unroll
                for (int q = 0; q < 4; ++q) {
                    float2 b = *(const float2*)(sB + (q * NKC + kc) * 64 + lane * 2);
                    mma8(acc[q], a, __float_as_uint(b.x), __float_as_uint(b.y));
                }
            }
            // cluster-wide empty arrive: stage free only when all 32 warps
            // across the 4-CTA cluster have finished reading it
            if (lane == 0) {
                #pragma unroll
                for (uint32_t rr = 0; rr < CLS; ++rr)
                    mbar_arrive_cluster(barB + 8 + cs * 16, rr);
            }
            cs ^= 1; if (cs == 0) cp ^= 1;
        }

        // ---- epilogue: gates, cell update (registers), publish h ----
        #pragma unroll
        for (int cr = 0; cr < 4; ++cr) {
            float gi, gf, gg, go;
            if (LAYER == 1) {
                gi = acc[0][cr] + bI[cr & 1]; gf = acc[1][cr] + bF[cr & 1];
                gg = acc[2][cr] + bG[cr & 1]; go = acc[3][cr] + bO[cr & 1];
            } else {
                gi = acc[0][cr] + xg[cr][0]; gf = acc[1][cr] + xg[cr][1];
                gg = acc[2][cr] + xg[cr][2]; go = acc[3][cr] + xg[cr][3];
            }
            float cn = sigf(gf) * creg[cr] + sigf(gi) * tanhf(gg);
            float hn = sigf(go) * tanhf(cn);
            creg[cr] = cn;
            float hr = tf32r(hn);
            int m = mrow[cr], j = j0 + (cr & 1);
            __stcg(&g_Hbuf[(rd ^ 1) * (BB * HH) + m * HH + j], hr);
            if (LAYER == 2) __stcg(&g_HS2[t * (BB * HH) + m * HH + j], hr);
            if (LAYER == 1 && t == nsteps - 1) __stcg(&g_C[m * HH + j], cn);
        }
        fence_async();     // generic stores -> async proxy (TMA) ordering
        grid_barrier();    // proven-correct CG barrier
        rd ^= 1;
    }
    cluster_sync();        // no CTA exits while peer multicasts could target it
}

// -------------------- one-shot GEMMs (XG2, final projection) --------------------
// MODE 2: XG2 = t_last @ Wi2 + b2   MODE 3: out = HS2 @ Wlin + blin
template<int MODE>
__global__ void __launch_bounds__(256)
gemm_kernel(const float* __restrict__ bias, float* __restrict__ out) {
    constexpr int NKC = NKC2;
    constexpr int NC  = HH / 32;

    __shared__ float sAs[2][4096];
    const int tid = threadIdx.x, w = tid >> 5, lane = tid & 31, cta = blockIdx.x;

    const float* Aptr = (MODE == 3) ? (g_HS2 + blockIdx.x * (BB * HH)) : g_Hbuf;
    const float* Wp   = (MODE == 3) ? g_Wlp : g_Wi2p;

    float acc[4][4];
    #pragma unroll
    for (int q = 0; q < 4; ++q)
        #pragma unroll
        for (int r = 0; r < 4; ++r) acc[q][r] = 0.0f;

    auto stage = [&](int c, float* dstbuf) {
        #pragma unroll
        for (int jj = 0; jj < 4; ++jj) {
            int s  = tid + jj * 256;
            int m  = s >> 3;
            int kq = s & 7;
            float4 v = *(const float4*)(Aptr + m * HH + c * 32 + kq * 4);
            int kk  = kq >> 1;
            int reg = (kq & 1) * 2 + ((m >> 3) & 1);
            int hi3 = (m & 7) ^ kq;
            *(float4*)(dstbuf + kk * 1024 + ((m >> 4) * 4 + reg) * 32 + hi3 * 4) = v;
        }
    };

    stage(0, sAs[0]);
    __syncthreads();

    for (int c = 0; c < NC; ++c) {
        const float* buf = sAs[c & 1];
        if (c + 1 < NC) stage(c + 1, sAs[(c + 1) & 1]);

        float2 bfr[4][4];
        #pragma unroll
        for (int kk = 0; kk < 4; ++kk) {
            int kc = c * 4 + kk;
            #pragma unroll
            for (int q = 0; q < 4; ++q) {
                int nt = (MODE == 3) ? (blockIdx.y * 4 + q) : (cta + q * 128);
                bfr[kk][q] = *(const float2*)(Wp + ((size_t)(nt * NKC + kc) * 32 + lane) * 2);
            }
        }

        #pragma unroll
        for (int kk = 0; kk < 4; ++kk) {
            uint32_t a[4];
            #pragma unroll
            for (int r = 0; r < 4; ++r) {
                int hi3 = (lane >> 2) ^ (kk * 2 + (r >> 1));
                a[r] = __float_as_uint(buf[kk * 1024 + (w * 4 + r) * 32 + hi3 * 4 + (lane & 3)]);
            }
            #pragma unroll
            for (int q = 0; q < 4; ++q)
                mma8(acc[q], a, __float_as_uint(bfr[kk][q].x), __float_as_uint(bfr[kk][q].y));
        }
        __syncthreads();
    }

    #pragma unroll
    for (int cr = 0; cr < 4; ++cr) {
        int m    = w * 16 + (lane >> 2) + ((cr >> 1) << 3);
        int jloc = (lane & 3) * 2 + (cr & 1);
        if (MODE == 3) {
            #pragma unroll
            for (int q = 0; q < 4; ++q) {
                int d = blockIdx.y * 32 + q * 8 + jloc;
                out[m * (TOUT * DOUT) + blockIdx.x * DOUT + d] = acc[q][cr] + bias[d];
            }
        } else {
            #pragma unroll
            for (int q = 0; q < 4; ++q) {
                int n = q * HH + cta * 8 + jloc;
                g_XG2[m * G4 + n] = acc[q][cr] + bias[n];
            }
        }
    }
}

// -------------------- launch --------------------
typedef CUresult (*EncodeFn)(CUtensorMap*, CUtensorMapDataType, cuuint32_t, void*,
                             const cuuint64_t*, const cuuint64_t*, const cuuint32_t*,
                             const cuuint32_t*, CUtensorMapInterleave, CUtensorMapSwizzle,
                             CUtensorMapL2promotion, CUtensorMapFloatOOBfill);

// smem: 1024B align slack + 64KB A ring + B slab + 128B barriers
#define SMEM1 (1024 + 65536 + 4 * NKC1 * 64 * 4 + 128)   // 205,952 B
#define SMEM2 (1024 + 65536 + 4 * NKC2 * 64 * 4 + 128)   // 197,760 B

extern "C" void kernel_launch(void* const* d_in, const int* in_sizes, int n_in,
                              void* d_out, int out_size) {
    const float* x    = (const float*)d_in[0];
    const float* Wi1  = (const float*)d_in[1];
    const float* Wh1  = (const float*)d_in[2];
    const float* b1   = (const float*)d_in[3];
    const float* Wi2  = (const float*)d_in[4];
    const float* Wh2  = (const float*)d_in[5];
    const float* b2   = (const float*)d_in[6];
    const float* Wlin = (const float*)d_in[7];
    const float* blin = (const float*)d_in[8];
    float* out = (float*)d_out;

    // ---- prep ----
    {
        int n;
        n = 512 * NKC1 * 64;
        permW_kernel<<<(n + 255) / 256, 256>>>(Wh1, Wi1, 0, NKC1, G4, n);
        n = 512 * NKC2 * 64;
        permW_kernel<<<(n + 255) / 256, 256>>>(Wh2, nullptr, 1, NKC2, G4, n);
        permW_kernel<<<(n + 255) / 256, 256>>>(Wi2, nullptr, 2, NKC2, G4, n);
        n = 16 * NKC2 * 64;
        permW_kernel<<<(n + 255) / 256, 256>>>(Wlin, nullptr, 3, NKC2, DOUT, n);
        n = BB * TIN * DIN;
        roundx_kernel<<<(n + 255) / 256, 256>>>(x, n);
        zero_kernel<<<(BB * HH + 255) / 256, 256>>>();
    }

    // ---- tensor maps (host-side, capture-legal) ----
    void* encP = nullptr;
    cudaDriverEntryPointQueryResult qr;
    cudaGetDriverEntryPointByVersion("cuTensorMapEncodeTiled", &encP, 12000,
                                     cudaEnableDefault, &qr);
    EncodeFn enc = (EncodeFn)encP;

    void* hAddr = nullptr; cudaGetSymbolAddress(&hAddr, g_Hbuf);
    void* xAddr = nullptr; cudaGetSymbolAddress(&xAddr, g_xr);

    CUtensorMap tmH, tmX;
    {
        // h: [1024 floats][128 rows][2 bufs]; box = 32 floats x 32 rows (slice)
        cuuint64_t dims[3] = {1024, 128, 2};
        cuuint64_t str[2]  = {4096, 524288};
        cuuint32_t box[3]  = {32, 32, 1};
        cuuint32_t es[3]   = {1, 1, 1};
        enc(&tmH, CU_TENSOR_MAP_DATA_TYPE_FLOAT32, 3, hAddr, dims, str, box, es,
            CU_TENSOR_MAP_INTERLEAVE_NONE, CU_TENSOR_MAP_SWIZZLE_128B,
            CU_TENSOR_MAP_L2_PROMOTION_L2_128B, CU_TENSOR_MAP_FLOAT_OOB_FILL_NONE);
    }
    {
        // x: [64 floats][256 t][128 batch]; box = 32 floats x 1 t x 32 batches (slice)
        cuuint64_t dims[3] = {64, 256, 128};
        cuuint64_t str[2]  = {256, 65536};
        cuuint32_t box[3]  = {32, 1, 32};
        cuuint32_t es[3]   = {1, 1, 1};
        enc(&tmX, CU_TENSOR_MAP_DATA_TYPE_FLOAT32, 3, xAddr, dims, str, box, es,
            CU_TENSOR_MAP_INTERLEAVE_NONE, CU_TENSOR_MAP_SWIZZLE_128B,
            CU_TENSOR_MAP_L2_PROMOTION_L2_128B, CU_TENSOR_MAP_FLOAT_OOB_FILL_NONE);
    }

    cudaFuncSetAttribute(lstm_persist<1>, cudaFuncAttributeMaxDynamicSharedMemorySize, SMEM1);
    cudaFuncSetAttribute(lstm_persist<2>, cudaFuncAttributeMaxDynamicSharedMemorySize, SMEM2);

    // ---- layer 1: 256 steps, persistent (32 clusters of 4) ----
    lstm_persist<1><<<NCTA, 256, SMEM1>>>(tmH, tmX, b1, TIN);
    // ---- xg2 = t_last @ Wi2 + b2 (t_last = g_Hbuf buffer 0 after 256 steps) ----
    gemm_kernel<2><<<128, 256>>>(b2, nullptr);
    // ---- layer 2: 128 steps, persistent (h,c carry over) ----
    lstm_persist<2><<<NCTA, 256, SMEM2>>>(tmH, tmX, nullptr, TOUT);
    // ---- final projection ----
    gemm_kernel<3><<<dim3(TOUT, 4), 256>>>(blin, out);
}

// round 13
// speedup vs baseline: 1.1507x; 1.1507x over previous
#include <cuda_runtime.h>
#include <cuda.h>
#include <cstdint>
#include <math.h>

#define BB   128
#define TIN  256
#define DIN  64
#define HH   1024
#define G4   4096
#define TOUT 128
#define DOUT 128

#define K1   (HH + DIN)   // 1088
#define NKC1 (K1 / 8)     // 136
#define NKC2 (HH / 8)     // 128
#define NCTA 128
#define NSTG 4            // A-ring stages (16KB each)

// -------------------- device scratch --------------------
__device__ float g_W1p [512 * NKC1 * 64];   // [Wh1;Wi1] permuted to B-frag order
__device__ float g_W2p [512 * NKC2 * 64];   // Wh2 permuted
__device__ float g_Wi2p[512 * NKC2 * 64];   // Wi2 permuted
__device__ float g_Wlp [ 16 * NKC2 * 64];   // Wlin permuted
__device__ __align__(256) float g_xr  [BB * TIN * DIN];
__device__ __align__(256) float g_Hbuf[2 * BB * HH];    // ping-pong hidden state
__device__ float g_C   [BB * HH];
__device__ float g_XG2 [BB * G4];
__device__ float g_HS2 [TOUT * BB * HH];
__device__ unsigned int g_bar;              // CG-style phase barrier counter

// -------------------- helpers --------------------
__device__ __forceinline__ float tf32r(float x) {
    uint32_t u;
    asm("cvt.rna.tf32.f32 %0, %1;" : "=r"(u) : "f"(x));
    return __uint_as_float(u);
}
__device__ __forceinline__ float sigf(float x) { return 1.0f / (1.0f + expf(-x)); }

__device__ __forceinline__ void mma8(float c[4], const uint32_t a[4], uint32_t b0, uint32_t b1) {
    asm volatile(
        "mma.sync.aligned.m16n8k8.row.col.f32.tf32.tf32.f32 "
        "{%0,%1,%2,%3}, {%4,%5,%6,%7}, {%8,%9}, {%0,%1,%2,%3};"
        : "+f"(c[0]), "+f"(c[1]), "+f"(c[2]), "+f"(c[3])
        : "r"(a[0]), "r"(a[1]), "r"(a[2]), "r"(a[3]), "r"(b0), "r"(b1));
}

__device__ __forceinline__ uint32_t s2u(const void* p) {
    uint32_t a;
    asm("{ .reg .u64 t; cvta.to.shared.u64 t, %1; cvt.u32.u64 %0, t; }" : "=r"(a) : "l"(p));
    return a;
}
__device__ __forceinline__ void mbar_init(uint32_t a, int cnt) {
    asm volatile("mbarrier.init.shared.b64 [%0], %1;" :: "r"(a), "r"(cnt) : "memory");
}
__device__ __forceinline__ void mbar_arrive(uint32_t a) {
    asm volatile("mbarrier.arrive.shared.b64 _, [%0];" :: "r"(a) : "memory");
}
__device__ __forceinline__ void mbar_expect(uint32_t a, uint32_t bytes) {
    asm volatile("mbarrier.arrive.expect_tx.shared.b64 _, [%0], %1;" :: "r"(a), "r"(bytes) : "memory");
}
__device__ __forceinline__ void mbar_wait(uint32_t a, int ph) {
    asm volatile(
        "{\n\t.reg .pred P;\n"
        "W%=:\n\t"
        "mbarrier.try_wait.parity.acquire.cta.shared::cta.b64 P, [%0], %1, 0x989680;\n\t"
        "@P bra D%=;\n\t"
        "bra W%=;\n"
        "D%=:\n\t}"
        :: "r"(a), "r"(ph) : "memory");
}
__device__ __forceinline__ void tma3d(uint32_t dst, const CUtensorMap* m,
                                      int x, int y, int z, uint32_t bar) {
    asm volatile(
        "cp.async.bulk.tensor.3d.shared::cta.global.tile.mbarrier::complete_tx::bytes "
        "[%0], [%1, {%2,%3,%4}], [%5];"
        :: "r"(dst), "l"(m), "r"(x), "r"(y), "r"(z), "r"(bar) : "memory");
}
__device__ __forceinline__ void fence_async() {
    asm volatile("fence.proxy.async;" ::: "memory");
}

// Cooperative-groups-style grid barrier (proven correct R9-R12).
__device__ __forceinline__ void grid_barrier() {
    __syncthreads();
    if (threadIdx.x == 0) {
        __threadfence();
        unsigned int nb = (blockIdx.x == 0) ? (0x80000000u - (NCTA - 1u)) : 1u;
        unsigned int old = atomicAdd(&g_bar, nb);
        volatile unsigned int* vb = &g_bar;
        while ((((old ^ *vb) & 0x80000000u) == 0u)) { }
        __threadfence();
    }
    __syncthreads();
}

// -------------------- prep kernels --------------------
__global__ void permW_kernel(const float* __restrict__ Wh, const float* __restrict__ Wx,
                             int which, int nkc, int ldsrc, int total) {
    int i = blockIdx.x * blockDim.x + threadIdx.x;
    if (i >= total) return;
    float* dst = (which == 0) ? g_W1p : (which == 1) ? g_W2p : (which == 2) ? g_Wi2p : g_Wlp;
    int reg  = i & 1;
    int lane = (i >> 1) & 31;
    int kc   = (i >> 6) % nkc;
    int nt   = i / (nkc * 64);
    int k = kc * 8 + reg * 4 + (lane & 3);
    int n = nt * 8 + (lane >> 2);
    float v = (k < HH) ? Wh[k * ldsrc + n] : Wx[(k - HH) * ldsrc + n];
    dst[i] = tf32r(v);
}

__global__ void roundx_kernel(const float* __restrict__ x, int total) {
    int i = blockIdx.x * blockDim.x + threadIdx.x;
    if (i < total) g_xr[i] = tf32r(x[i]);
}

__global__ void zero_kernel() {
    int i = blockIdx.x * blockDim.x + threadIdx.x;
    if (i < BB * HH) { g_Hbuf[i] = 0.0f; g_Hbuf[BB * HH + i] = 0.0f; g_C[i] = 0.0f; }
    if (i == 0) g_bar = 0u;
}

// -------------------- persistent LSTM layer kernel --------------------
// 128 CTAs x 288 thr, one CTA per SM (single wave -> grid barrier safe).
// WARP-SPECIALIZED: warps 0-7 = consumers (tf32 mma), thread 256 (warp 8)
// = dedicated TMA producer. 4-stage ring of 16KB A chunks (128 rows x 32 k,
// SW128, 1024B-aligned) so the producer runs up to 3 chunks ahead and TMA
// latency never enters the consumer critical path. B weights SMEM-resident.
// Cell state in registers. CG grid barrier between steps; proxy fence
// orders generic h-stores before async-proxy TMA reads (R11-proven).
template<int LAYER>
__global__ void __launch_bounds__(288)
lstm_persist(const __grid_constant__ CUtensorMap tmH,
             const __grid_constant__ CUtensorMap tmX,
             const float* __restrict__ bias, int nsteps)
{
    constexpr int NKC = (LAYER == 1) ? NKC1 : NKC2;
    constexpr int NC  = (LAYER == 1) ? 34 : 32;     // 32-k chunks per step

    extern __shared__ float smraw[];
    const uint32_t rawB = s2u(smraw);
    const uint32_t aB   = (rawB + 1023u) & ~1023u;  // 1024B-aligned TMA ring
    float* sA = smraw + ((aB - rawB) >> 2);          // NSTG x 4096 floats
    float* sB = sA + NSTG * 4096;                    // B slab, fragment order
    const uint32_t barB = s2u(sB + 4 * NKC * 64);    // per stage: full@+0, empty@+8

    const int tid = threadIdx.x, w = tid >> 5, lane = tid & 31, cta = blockIdx.x;
    const bool producer = (tid == 256);
    const bool consumer = (tid < 256);

    // ---- load B slabs into SMEM (once per layer) ----
    {
        const float* Wp = (LAYER == 1) ? g_W1p : g_W2p;
        #pragma unroll
        for (int q = 0; q < 4; ++q) {
            const float4* src = (const float4*)(Wp + (size_t)(cta + q * 128) * (NKC * 64));
            float4* dst = (float4*)(sB + q * NKC * 64);
            for (int i = tid; i < NKC * 16; i += 288) dst[i] = src[i];
        }
    }
    if (tid == 0) {
        #pragma unroll
        for (int s = 0; s < NSTG; ++s) {
            mbar_init(barB + s * 16 + 0, 1);   // full: one expect_tx arrive
            mbar_init(barB + s * 16 + 8, 8);   // empty: 8 consumer warps
        }
        asm volatile("fence.proxy.async.shared::cta;" ::: "memory");
    }

    // ---- per-thread constants (consumers only; producer lanes would OOB) ----
    const int j0 = cta * 8 + (lane & 3) * 2;
    int mrow[4];
    #pragma unroll
    for (int cr = 0; cr < 4; ++cr) mrow[cr] = (w & 7) * 16 + (lane >> 2) + ((cr >> 1) << 3);

    float bI[2], bF[2], bG[2], bO[2];
    float xg[4][4];
    float creg[4] = {0.f, 0.f, 0.f, 0.f};
    if (consumer) {
        if (LAYER == 1) {
            #pragma unroll
            for (int u = 0; u < 2; ++u) {
                bI[u] = bias[j0 + u];          bF[u] = bias[HH + j0 + u];
                bG[u] = bias[2 * HH + j0 + u]; bO[u] = bias[3 * HH + j0 + u];
            }
        } else {
            #pragma unroll
            for (int cr = 0; cr < 4; ++cr) {
                int m = mrow[cr], j = j0 + (cr & 1);
                xg[cr][0] = __ldcg(&g_XG2[m * G4 + j]);
                xg[cr][1] = __ldcg(&g_XG2[m * G4 + HH + j]);
                xg[cr][2] = __ldcg(&g_XG2[m * G4 + 2 * HH + j]);
                xg[cr][3] = __ldcg(&g_XG2[m * G4 + 3 * HH + j]);
                creg[cr]  = __ldcg(&g_C[m * HH + j]);
            }
        }
    }
    __syncthreads();

    int ps = 0, pp = 1, cs = 0, cp = 0;   // producer / consumer stage+phase
    int rd = 0;

    for (int t = 0; t < nsteps; ++t) {
        if (producer) {
            // ---- dedicated TMA producer: stream all chunks of this step ----
            fence_async();   // order prior generic h-stores before async reads
            for (int c = 0; c < NC; ++c) {
                mbar_wait(barB + ps * 16 + 8, pp);
                mbar_expect(barB + ps * 16, 16384);
                uint32_t d = aB + ps * 16384;
                if (LAYER == 1 && c >= 32)
                    tma3d(d, &tmX, (c - 32) * 32, t, 0, barB + ps * 16);
                else
                    tma3d(d, &tmH, c * 32, 0, rd, barB + ps * 16);
                ps = (ps + 1) & (NSTG - 1); if (ps == 0) pp ^= 1;
            }
        }

        float acc[4][4];
        #pragma unroll
        for (int q = 0; q < 4; ++q) {
            #pragma unroll
            for (int r = 0; r < 4; ++r) acc[q][r] = 0.f;
        }

        if (consumer) {
            for (int c = 0; c < NC; ++c) {
                mbar_wait(barB + cs * 16, cp);
                const float* hb = sA + cs * 4096;

                #pragma unroll
                for (int kk = 0; kk < 4; ++kk) {
                    int kc = c * 4 + kk;
                    uint32_t a[4];
                    #pragma unroll
                    for (int r = 0; r < 4; ++r) {
                        int m    = (w & 7) * 16 + (lane >> 2) + (r & 1) * 8;
                        int colw = kk * 8 + (lane & 3) + ((r >> 1) << 2);
                        a[r] = __float_as_uint(hb[m * 32 + (colw ^ ((m & 7) << 2))]);
                    }
                    #pragma unroll
                    for (int q = 0; q < 4; ++q) {
                        float2 b = *(const float2*)(sB + (q * NKC + kc) * 64 + lane * 2);
                        mma8(acc[q], a, __float_as_uint(b.x), __float_as_uint(b.y));
                    }
                }
                if (lane == 0) mbar_arrive(barB + cs * 16 + 8);
                cs = (cs + 1) & (NSTG - 1); if (cs == 0) cp ^= 1;
            }

            // ---- epilogue: gates, cell update (registers), publish h ----
            #pragma unroll
            for (int cr = 0; cr < 4; ++cr) {
                float gi, gf, gg, go;
                if (LAYER == 1) {
                    gi = acc[0][cr] + bI[cr & 1]; gf = acc[1][cr] + bF[cr & 1];
                    gg = acc[2][cr] + bG[cr & 1]; go = acc[3][cr] + bO[cr & 1];
                } else {
                    gi = acc[0][cr] + xg[cr][0]; gf = acc[1][cr] + xg[cr][1];
                    gg = acc[2][cr] + xg[cr][2]; go = acc[3][cr] + xg[cr][3];
                }
                float cn = sigf(gf) * creg[cr] + sigf(gi) * tanhf(gg);
                float hn = sigf(go) * tanhf(cn);
                creg[cr] = cn;
                float hr = tf32r(hn);
                int m = mrow[cr], j = j0 + (cr & 1);
                __stcg(&g_Hbuf[(rd ^ 1) * (BB * HH) + m * HH + j], hr);
                if (LAYER == 2) __stcg(&g_HS2[t * (BB * HH) + m * HH + j], hr);
                if (LAYER == 1 && t == nsteps - 1) __stcg(&g_C[m * HH + j], cn);
            }
        }

        grid_barrier();    // proven-correct CG barrier (also syncs producer)
        rd ^= 1;
    }
}

// -------------------- one-shot GEMMs (XG2, final projection) --------------------
// MODE 2: XG2 = t_last @ Wi2 + b2   MODE 3: out = HS2 @ Wlin + blin
template<int MODE>
__global__ void __launch_bounds__(256)
gemm_kernel(const float* __restrict__ bias, float* __restrict__ out) {
    constexpr int NKC = NKC2;
    constexpr int NC  = HH / 32;

    __shared__ float sAs[2][4096];
    const int tid = threadIdx.x, w = tid >> 5, lane = tid & 31, cta = blockIdx.x;

    const float* Aptr = (MODE == 3) ? (g_HS2 + blockIdx.x * (BB * HH)) : g_Hbuf;
    const float* Wp   = (MODE == 3) ? g_Wlp : g_Wi2p;

    float acc[4][4];
    #pragma unroll
    for (int q = 0; q < 4; ++q)
        #pragma unroll
        for (int r = 0; r < 4; ++r) acc[q][r] = 0.0f;

    auto stage = [&](int c, float* dstbuf) {
        #pragma unroll
        for (int jj = 0; jj < 4; ++jj) {
            int s  = tid + jj * 256;
            int m  = s >> 3;
            int kq = s & 7;
            float4 v = *(const float4*)(Aptr + m * HH + c * 32 + kq * 4);
            int kk  = kq >> 1;
            int reg = (kq & 1) * 2 + ((m >> 3) & 1);
            int hi3 = (m & 7) ^ kq;
            *(float4*)(dstbuf + kk * 1024 + ((m >> 4) * 4 + reg) * 32 + hi3 * 4) = v;
        }
    };

    stage(0, sAs[0]);
    __syncthreads();

    for (int c = 0; c < NC; ++c) {
        const float* buf = sAs[c & 1];
        if (c + 1 < NC) stage(c + 1, sAs[(c + 1) & 1]);

        float2 bfr[4][4];
        #pragma unroll
        for (int kk = 0; kk < 4; ++kk) {
            int kc = c * 4 + kk;
            #pragma unroll
            for (int q = 0; q < 4; ++q) {
                int nt = (MODE == 3) ? (blockIdx.y * 4 + q) : (cta + q * 128);
                bfr[kk][q] = *(const float2*)(Wp + ((size_t)(nt * NKC + kc) * 32 + lane) * 2);
            }
        }

        #pragma unroll
        for (int kk = 0; kk < 4; ++kk) {
            uint32_t a[4];
            #pragma unroll
            for (int r = 0; r < 4; ++r) {
                int hi3 = (lane >> 2) ^ (kk * 2 + (r >> 1));
                a[r] = __float_as_uint(buf[kk * 1024 + (w * 4 + r) * 32 + hi3 * 4 + (lane & 3)]);
            }
            #pragma unroll
            for (int q = 0; q < 4; ++q)
                mma8(acc[q], a, __float_as_uint(bfr[kk][q].x), __float_as_uint(bfr[kk][q].y));
        }
        __syncthreads();
    }

    #pragma unroll
    for (int cr = 0; cr < 4; ++cr) {
        int m    = w * 16 + (lane >> 2) + ((cr >> 1) << 3);
        int jloc = (lane & 3) * 2 + (cr & 1);
        if (MODE == 3) {
            #pragma unroll
            for (int q = 0; q < 4; ++q) {
                int d = blockIdx.y * 32 + q * 8 + jloc;
                out[m * (TOUT * DOUT) + blockIdx.x * DOUT + d] = acc[q][cr] + bias[d];
            }
        } else {
            #pragma unroll
            for (int q = 0; q < 4; ++q) {
                int n = q * HH + cta * 8 + jloc;
                g_XG2[m * G4 + n] = acc[q][cr] + bias[n];
            }
        }
    }
}

// -------------------- launch --------------------
typedef CUresult (*EncodeFn)(CUtensorMap*, CUtensorMapDataType, cuuint32_t, void*,
                             const cuuint64_t*, const cuuint64_t*, const cuuint32_t*,
                             const cuuint32_t*, CUtensorMapInterleave, CUtensorMapSwizzle,
                             CUtensorMapL2promotion, CUtensorMapFloatOOBfill);

// smem: 1024B align slack + 64KB A ring (4x16KB) + B slab + barrier block
#define SMEM1 (1024 + 65536 + 4 * NKC1 * 64 * 4 + 128)   // 205,952 B
#define SMEM2 (1024 + 65536 + 4 * NKC2 * 64 * 4 + 128)   // 197,760 B

extern "C" void kernel_launch(void* const* d_in, const int* in_sizes, int n_in,
                              void* d_out, int out_size) {
    const float* x    = (const float*)d_in[0];
    const float* Wi1  = (const float*)d_in[1];
    const float* Wh1  = (const float*)d_in[2];
    const float* b1   = (const float*)d_in[3];
    const float* Wi2  = (const float*)d_in[4];
    const float* Wh2  = (const float*)d_in[5];
    const float* b2   = (const float*)d_in[6];
    const float* Wlin = (const float*)d_in[7];
    const float* blin = (const float*)d_in[8];
    float* out = (float*)d_out;

    // ---- prep ----
    {
        int n;
        n = 512 * NKC1 * 64;
        permW_kernel<<<(n + 255) / 256, 256>>>(Wh1, Wi1, 0, NKC1, G4, n);
        n = 512 * NKC2 * 64;
        permW_kernel<<<(n + 255) / 256, 256>>>(Wh2, nullptr, 1, NKC2, G4, n);
        permW_kernel<<<(n + 255) / 256, 256>>>(Wi2, nullptr, 2, NKC2, G4, n);
        n = 16 * NKC2 * 64;
        permW_kernel<<<(n + 255) / 256, 256>>>(Wlin, nullptr, 3, NKC2, DOUT, n);
        n = BB * TIN * DIN;
        roundx_kernel<<<(n + 255) / 256, 256>>>(x, n);
        zero_kernel<<<(BB * HH + 255) / 256, 256>>>();
    }

    // ---- tensor maps (host-side, capture-legal; R11-proven) ----
    void* encP = nullptr;
    cudaDriverEntryPointQueryResult qr;
    cudaGetDriverEntryPointByVersion("cuTensorMapEncodeTiled", &encP, 12000,
                                     cudaEnableDefault, &qr);
    EncodeFn enc = (EncodeFn)encP;

    void* hAddr = nullptr; cudaGetSymbolAddress(&hAddr, g_Hbuf);
    void* xAddr = nullptr; cudaGetSymbolAddress(&xAddr, g_xr);

    CUtensorMap tmH, tmX;
    {
        // h: [1024 floats][128 rows][2 bufs]; box = 32 floats x 128 rows (16KB)
        cuuint64_t dims[3] = {1024, 128, 2};
        cuuint64_t str[2]  = {4096, 524288};
        cuuint32_t box[3]  = {32, 128, 1};
        cuuint32_t es[3]   = {1, 1, 1};
        enc(&tmH, CU_TENSOR_MAP_DATA_TYPE_FLOAT32, 3, hAddr, dims, str, box, es,
            CU_TENSOR_MAP_INTERLEAVE_NONE, CU_TENSOR_MAP_SWIZZLE_128B,
            CU_TENSOR_MAP_L2_PROMOTION_L2_128B, CU_TENSOR_MAP_FLOAT_OOB_FILL_NONE);
    }
    {
        // x: [64 floats][256 t][128 batch]; box = 32 floats x 1 t x 128 batches (16KB)
        cuuint64_t dims[3] = {64, 256, 128};
        cuuint64_t str[2]  = {256, 65536};
        cuuint32_t box[3]  = {32, 1, 128};
        cuuint32_t es[3]   = {1, 1, 1};
        enc(&tmX, CU_TENSOR_MAP_DATA_TYPE_FLOAT32, 3, xAddr, dims, str, box, es,
            CU_TENSOR_MAP_INTERLEAVE_NONE, CU_TENSOR_MAP_SWIZZLE_128B,
            CU_TENSOR_MAP_L2_PROMOTION_L2_128B, CU_TENSOR_MAP_FLOAT_OOB_FILL_NONE);
    }

    cudaFuncSetAttribute(lstm_persist<1>, cudaFuncAttributeMaxDynamicSharedMemorySize, SMEM1);
    cudaFuncSetAttribute(lstm_persist<2>, cudaFuncAttributeMaxDynamicSharedMemorySize, SMEM2);

    // ---- layer 1: 256 steps, persistent, warp-specialized ----
    lstm_persist<1><<<NCTA, 288, SMEM1>>>(tmH, tmX, b1, TIN);
    // ---- xg2 = t_last @ Wi2 + b2 (t_last = g_Hbuf buffer 0 after 256 steps) ----
    gemm_kernel<2><<<128, 256>>>(b2, nullptr);
    // ---- layer 2: 128 steps, persistent (h,c carry over) ----
    lstm_persist<2><<<NCTA, 288, SMEM2>>>(tmH, tmX, nullptr, TOUT);
    // ---- final projection ----
    gemm_kernel<3><<<dim3(TOUT, 4), 256>>>(blin, out);
}